// round 2
// baseline (speedup 1.0000x reference)
#include <cuda_runtime.h>
#include <cstdint>

// Problem constants
#define BATCH   2
#define SEQ     2048
#define DIMV    4096
#define HQ      32
#define HKV     8
#define NREP    4
#define HD      128
#define ROWS    (BATCH * SEQ)      // 4096
#define KVDIM   (HKV * HD)         // 1024

// Intermediate buffers (allocation-free rule: __device__ globals)
__device__ float g_q[ROWS * DIMV];     // 64 MB  [B,S,HQ,HD]
__device__ float g_k[ROWS * KVDIM];    // 16 MB  [B,S,HKV,HD]
__device__ float g_v[ROWS * KVDIM];    // 16 MB
__device__ float g_att[ROWS * DIMV];   // 64 MB  [B,S,HQ,HD] == [ROWS, DIMV]

// ---------------------------------------------------------------------------
// Packed f32x2 helpers (Blackwell: fma.rn.f32x2 doubles fp32 FFMA throughput)
// ---------------------------------------------------------------------------
__device__ __forceinline__ unsigned long long pack2(float lo, float hi) {
    unsigned long long r;
    asm("mov.b64 %0, {%1, %2};" : "=l"(r) : "f"(lo), "f"(hi));
    return r;
}
__device__ __forceinline__ unsigned long long ffma2(unsigned long long a,
                                                    unsigned long long b,
                                                    unsigned long long c) {
    unsigned long long d;
    asm("fma.rn.f32x2 %0, %1, %2, %3;" : "=l"(d) : "l"(a), "l"(b), "l"(c));
    return d;
}
__device__ __forceinline__ float2 unpack2(unsigned long long v) {
    float2 f;
    asm("mov.b64 {%0, %1}, %2;" : "=f"(f.x), "=f"(f.y) : "l"(v));
    return f;
}

// ---------------------------------------------------------------------------
// SGEMM: C[M,N] = A[M,K] @ B[K,N], all row-major, fp32.
// 128x128 tile, BK=8, 256 threads, 8x8 microtile, packed f32x2 FMA inner loop.
// All dims here are multiples of 128 (M,N) and 8 (K).
// ---------------------------------------------------------------------------
__global__ __launch_bounds__(256) void sgemm_f32(
    const float* __restrict__ A, const float* __restrict__ B,
    float* __restrict__ C, int M, int N, int K)
{
    __shared__ float As[8][132];   // padded: conflict-free scattered stores
    __shared__ float Bs[8][132];

    const int bx = blockIdx.x;     // N tile
    const int by = blockIdx.y;     // M tile
    const int tid = threadIdx.x;
    const int tc = tid & 15;       // 0..15 col group
    const int tr = tid >> 4;       // 0..15 row group

    const int arow = tid >> 1;           // 0..127
    const int acol = (tid & 1) << 2;     // 0 or 4
    const int brow = tid >> 5;           // 0..7
    const int bcol = (tid & 31) << 2;    // 0..124

    const float* Ab = A + by * 128 * K;
    const float* Bb = B + bx * 128;

    unsigned long long acc[8][4];
    #pragma unroll
    for (int i = 0; i < 8; i++)
        #pragma unroll
        for (int j = 0; j < 4; j++) acc[i][j] = 0ULL;   // (0.0f, 0.0f)

    for (int k0 = 0; k0 < K; k0 += 8) {
        float4 a4 = *(const float4*)&Ab[arow * K + k0 + acol];
        As[acol + 0][arow] = a4.x;
        As[acol + 1][arow] = a4.y;
        As[acol + 2][arow] = a4.z;
        As[acol + 3][arow] = a4.w;
        float4 b4 = *(const float4*)&Bb[(k0 + brow) * N + bcol];
        *(float4*)&Bs[brow][bcol] = b4;
        __syncthreads();

        #pragma unroll
        for (int k = 0; k < 8; k++) {
            float4 a0 = *(const float4*)&As[k][tr * 8];
            float4 a1 = *(const float4*)&As[k][tr * 8 + 4];
            unsigned long long bb[4];
            #pragma unroll
            for (int t = 0; t < 4; t++)
                bb[t] = *(const unsigned long long*)&Bs[k][tc * 8 + 2 * t];
            float af[8] = {a0.x, a0.y, a0.z, a0.w, a1.x, a1.y, a1.z, a1.w};
            #pragma unroll
            for (int i = 0; i < 8; i++) {
                unsigned long long pa = pack2(af[i], af[i]);
                #pragma unroll
                for (int t = 0; t < 4; t++)
                    acc[i][t] = ffma2(pa, bb[t], acc[i][t]);
            }
        }
        __syncthreads();
    }

    #pragma unroll
    for (int i = 0; i < 8; i++) {
        int row = by * 128 + tr * 8 + i;
        float* cp = &C[row * N + bx * 128 + tc * 8];
        float2 v0 = unpack2(acc[i][0]);
        float2 v1 = unpack2(acc[i][1]);
        float2 v2 = unpack2(acc[i][2]);
        float2 v3 = unpack2(acc[i][3]);
        float4 w0 = make_float4(v0.x, v0.y, v1.x, v1.y);
        float4 w1 = make_float4(v2.x, v2.y, v3.x, v3.y);
        *(float4*)&cp[0] = w0;
        *(float4*)&cp[4] = w1;
    }
}

// ---------------------------------------------------------------------------
// Flash attention (fp32, online softmax). One block = 64 queries of one (b,h).
// 256 threads: rg = tid>>3 (0..31) owns 2 query rows; cg = tid&7 owns
// 8 key cols (score phase) / 16 head dims (output phase).
// SMEM: Qs[d][r] 32KB, Ks[d][k] 32KB, Vs[k][d] 32KB, Ps[k][r] 16KB = 112KB.
// ---------------------------------------------------------------------------
#define BQ 64
#define BKV 64
#define FLASH_SMEM ((128*64 + 128*64 + 64*128 + 64*64) * 4)

__global__ __launch_bounds__(256) void flash_attn(
    const float* __restrict__ Q, const float* __restrict__ Kg,
    const float* __restrict__ Vg, float* __restrict__ Og)
{
    extern __shared__ float sm[];
    float* Qs = sm;                 // [128][64]
    float* Ks = Qs + 128 * 64;      // [128][64]
    float* Vs = Ks + 128 * 64;      // [64][128]
    float* Ps = Vs + 64 * 128;      // [64][64]

    const int qb = blockIdx.x;
    const int h  = blockIdx.y;
    const int b  = blockIdx.z;
    const int kvh = h >> 2;         // h / NREP
    const int tid = threadIdx.x;
    const int rg = tid >> 3;        // 0..31
    const int cg = tid & 7;         // 0..7
    const int r0 = rg * 2;
    const float scale = 0.08838834764831845f;  // 1/sqrt(128)

    // Load Q tile transposed+scaled: Qs[d][r]
    for (int i = tid; i < BQ * 32; i += 256) {
        int r  = i >> 5;
        int d4 = (i & 31) << 2;
        int q  = qb * BQ + r;
        float4 v4 = *(const float4*)&Q[(((b * SEQ + q) * HQ + h) << 7) + d4];
        Qs[(d4 + 0) * 64 + r] = v4.x * scale;
        Qs[(d4 + 1) * 64 + r] = v4.y * scale;
        Qs[(d4 + 2) * 64 + r] = v4.z * scale;
        Qs[(d4 + 3) * 64 + r] = v4.w * scale;
    }

    float o[2][16];
    #pragma unroll
    for (int i = 0; i < 2; i++)
        #pragma unroll
        for (int t = 0; t < 16; t++) o[i][t] = 0.0f;
    float mr[2] = {-1e30f, -1e30f};
    float lr[2] = {0.0f, 0.0f};

    const int qg0 = qb * BQ + r0;   // hoisted: global row of this thread's q0
    const int kc0 = cg * 8;         // hoisted: this thread's first key col in tile

    const int nkb = qb + 1;  // causal: key blocks 0..qb
    for (int kb = 0; kb < nkb; kb++) {
        __syncthreads();   // protect Ks/Vs (and Ps) against previous iter readers
        for (int i = tid; i < BKV * 32; i += 256) {
            int r  = i >> 5;
            int d4 = (i & 31) << 2;
            int kk = kb * BKV + r;
            int base = ((b * SEQ + kk) * HKV + kvh) * HD + d4;
            float4 k4 = *(const float4*)&Kg[base];
            Ks[(d4 + 0) * 64 + r] = k4.x;
            Ks[(d4 + 1) * 64 + r] = k4.y;
            Ks[(d4 + 2) * 64 + r] = k4.z;
            Ks[(d4 + 3) * 64 + r] = k4.w;
            float4 vv = *(const float4*)&Vg[base];
            *(float4*)&Vs[r * 128 + d4] = vv;
        }
        __syncthreads();

        // Score phase: s[2][8] = Q[2 rows] . K[8 cols] over d=128
        float s[2][8];
        #pragma unroll
        for (int i = 0; i < 2; i++)
            #pragma unroll
            for (int j = 0; j < 8; j++) s[i][j] = 0.0f;

        #pragma unroll 4
        for (int d = 0; d < 128; d++) {
            float2 q2 = *(const float2*)&Qs[d * 64 + r0];
            float4 ka = *(const float4*)&Ks[d * 64 + kc0];
            float4 kb4 = *(const float4*)&Ks[d * 64 + kc0 + 4];
            float kf[8] = {ka.x, ka.y, ka.z, ka.w, kb4.x, kb4.y, kb4.z, kb4.w};
            #pragma unroll
            for (int j = 0; j < 8; j++) {
                s[0][j] += q2.x * kf[j];
                s[1][j] += q2.y * kf[j];
            }
        }

        // Causal mask (only on the diagonal block)
        if (kb == qb) {
            int kg0 = kb * BKV + kc0;
            #pragma unroll
            for (int i = 0; i < 2; i++)
                #pragma unroll
                for (int j = 0; j < 8; j++)
                    if (kg0 + j > qg0 + i) s[i][j] = -1e30f;
        }

        // Online softmax per row (8 threads per row: shfl over lane bits 0..2)
        #pragma unroll
        for (int i = 0; i < 2; i++) {
            float mx = s[i][0];
            #pragma unroll
            for (int j = 1; j < 8; j++) mx = fmaxf(mx, s[i][j]);
            #pragma unroll
            for (int off = 1; off < 8; off <<= 1)
                mx = fmaxf(mx, __shfl_xor_sync(0xffffffffu, mx, off));
            float mnew = fmaxf(mr[i], mx);
            float corr = __expf(mr[i] - mnew);
            mr[i] = mnew;
            float ps = 0.0f;
            #pragma unroll
            for (int j = 0; j < 8; j++) {
                float p = __expf(s[i][j] - mnew);
                ps += p;
                Ps[(kc0 + j) * 64 + r0 + i] = p;
            }
            #pragma unroll
            for (int off = 1; off < 8; off <<= 1)
                ps += __shfl_xor_sync(0xffffffffu, ps, off);
            lr[i] = lr[i] * corr + ps;
            #pragma unroll
            for (int t = 0; t < 16; t++) o[i][t] *= corr;
        }
        __syncwarp();  // P exchange is intra-warp (same rg -> same warp)

        // Output phase: o[2][16] += P[2 rows][kk] * V[kk][16 dims]
        #pragma unroll 2
        for (int kk = 0; kk < BKV; kk++) {
            float2 p2 = *(const float2*)&Ps[kk * 64 + r0];
            const float* vrow = &Vs[kk * 128 + cg * 16];
            float4 v0 = *(const float4*)&vrow[0];
            float4 v1 = *(const float4*)&vrow[4];
            float4 v2 = *(const float4*)&vrow[8];
            float4 v3 = *(const float4*)&vrow[12];
            float vf[16] = {v0.x, v0.y, v0.z, v0.w, v1.x, v1.y, v1.z, v1.w,
                            v2.x, v2.y, v2.z, v2.w, v3.x, v3.y, v3.z, v3.w};
            #pragma unroll
            for (int t = 0; t < 16; t++) {
                o[0][t] += p2.x * vf[t];
                o[1][t] += p2.y * vf[t];
            }
        }
    }

    // Normalize and write: Og layout [B,S,HQ,HD]
    #pragma unroll
    for (int i = 0; i < 2; i++) {
        float inv = 1.0f / lr[i];
        int q = qb * BQ + r0 + i;
        float* outp = &Og[(((b * SEQ + q) * HQ + h) << 7) + cg * 16];
        #pragma unroll
        for (int t4 = 0; t4 < 4; t4++) {
            float4 w = make_float4(o[i][4 * t4 + 0] * inv, o[i][4 * t4 + 1] * inv,
                                   o[i][4 * t4 + 2] * inv, o[i][4 * t4 + 3] * inv);
            *(float4*)&outp[4 * t4] = w;
        }
    }
}

// ---------------------------------------------------------------------------
extern "C" void kernel_launch(void* const* d_in, const int* in_sizes, int n_in,
                              void* d_out, int out_size)
{
    const float* x  = (const float*)d_in[0];
    const float* wq = (const float*)d_in[1];
    const float* wk = (const float*)d_in[2];
    const float* wv = (const float*)d_in[3];
    const float* wo = (const float*)d_in[4];
    // d_in[5] = start_pos (always 0 in this problem) — ignored.
    float* out = (float*)d_out;

    float *q, *k, *v, *att;
    cudaGetSymbolAddress((void**)&q,   g_q);
    cudaGetSymbolAddress((void**)&k,   g_k);
    cudaGetSymbolAddress((void**)&v,   g_v);
    cudaGetSymbolAddress((void**)&att, g_att);

    cudaFuncSetAttribute(flash_attn, cudaFuncAttributeMaxDynamicSharedMemorySize,
                         FLASH_SMEM);

    dim3 gq(DIMV / 128, ROWS / 128);    // (32, 32)
    dim3 gkv(KVDIM / 128, ROWS / 128);  // (8, 32)

    sgemm_f32<<<gq, 256>>>(x, wq, q, ROWS, DIMV, DIMV);
    sgemm_f32<<<gkv, 256>>>(x, wk, k, ROWS, KVDIM, DIMV);
    sgemm_f32<<<gkv, 256>>>(x, wv, v, ROWS, KVDIM, DIMV);
    flash_attn<<<dim3(SEQ / BQ, HQ, BATCH), 256, FLASH_SMEM>>>(q, k, v, att);
    sgemm_f32<<<gq, 256>>>(att, wo, out, ROWS, DIMV, DIMV);
}

// round 7
// speedup vs baseline: 1.5482x; 1.5482x over previous
#include <cuda_runtime.h>
#include <cuda_bf16.h>
#include <cstdint>

// Problem constants
#define BATCH   2
#define SEQ     2048
#define DIMV    4096
#define HQ      32
#define HKV     8
#define HD      128
#define ROWS    (BATCH * SEQ)      // 4096
#define KVDIM   (HKV * HD)         // 1024

// ---------------------------------------------------------------------------
// Device scratch (allocation-free rule)
// ---------------------------------------------------------------------------
__device__ float g_q[ROWS * DIMV];
__device__ float g_k[ROWS * KVDIM];
__device__ float g_v[ROWS * KVDIM];
__device__ float g_att[ROWS * DIMV];

__device__ __nv_bfloat16 g_xhi[ROWS * DIMV],  g_xlo[ROWS * DIMV];
__device__ __nv_bfloat16 g_ahi[ROWS * DIMV],  g_alo[ROWS * DIMV];
__device__ __nv_bfloat16 g_wqThi[DIMV * DIMV],  g_wqTlo[DIMV * DIMV];
__device__ __nv_bfloat16 g_wkThi[KVDIM * DIMV], g_wkTlo[KVDIM * DIMV];
__device__ __nv_bfloat16 g_wvThi[KVDIM * DIMV], g_wvTlo[KVDIM * DIMV];
__device__ __nv_bfloat16 g_woThi[DIMV * DIMV],  g_woTlo[DIMV * DIMV];

// ---------------------------------------------------------------------------
// Arch-generic PTX helpers (NO 'a'-gated instructions: sm_103 virtual target)
// ---------------------------------------------------------------------------
__device__ __forceinline__ uint32_t smem_u32(const void* p) {
    uint32_t a;
    asm("{ .reg .u64 t; cvta.to.shared.u64 t, %1; cvt.u32.u64 %0, t; }"
        : "=r"(a) : "l"(p));
    return a;
}

#define CP_ASYNC16(saddr, gptr) \
    asm volatile("cp.async.cg.shared.global [%0], [%1], 16;" \
        :: "r"(saddr), "l"(gptr) : "memory")
#define CP_COMMIT()  asm volatile("cp.async.commit_group;" ::: "memory")
#define CP_WAIT1()   asm volatile("cp.async.wait_group 1;" ::: "memory")
#define CP_WAIT0()   asm volatile("cp.async.wait_group 0;" ::: "memory")

__device__ __forceinline__ void ldsm4(uint32_t* r, uint32_t addr) {
    asm volatile("ldmatrix.sync.aligned.m8n8.x4.shared.b16 {%0,%1,%2,%3}, [%4];"
        : "=r"(r[0]), "=r"(r[1]), "=r"(r[2]), "=r"(r[3]) : "r"(addr));
}

__device__ __forceinline__ void mma16816(float* d, const uint32_t* a, const uint32_t* b) {
    asm volatile("mma.sync.aligned.m16n8k16.row.col.f32.bf16.bf16.f32 "
        "{%0,%1,%2,%3}, {%4,%5,%6,%7}, {%8,%9}, {%0,%1,%2,%3};"
        : "+f"(d[0]), "+f"(d[1]), "+f"(d[2]), "+f"(d[3])
        : "r"(a[0]), "r"(a[1]), "r"(a[2]), "r"(a[3]), "r"(b[0]), "r"(b[1]));
}

// ---------------------------------------------------------------------------
// Split fp32 -> bf16 hi/lo (row-major, elementwise)
// ---------------------------------------------------------------------------
__global__ __launch_bounds__(256) void split_rm(
    const float4* __restrict__ in, __nv_bfloat16* __restrict__ hi,
    __nv_bfloat16* __restrict__ lo, int n4)
{
    int i = blockIdx.x * 256 + threadIdx.x;
    if (i >= n4) return;
    float4 v = in[i];
    __nv_bfloat16 h0 = __float2bfloat16(v.x), h1 = __float2bfloat16(v.y);
    __nv_bfloat16 h2 = __float2bfloat16(v.z), h3 = __float2bfloat16(v.w);
    __nv_bfloat16 l0 = __float2bfloat16(v.x - __bfloat162float(h0));
    __nv_bfloat16 l1 = __float2bfloat16(v.y - __bfloat162float(h1));
    __nv_bfloat16 l2 = __float2bfloat16(v.z - __bfloat162float(h2));
    __nv_bfloat16 l3 = __float2bfloat16(v.w - __bfloat162float(h3));
    __nv_bfloat162* H = (__nv_bfloat162*)hi;
    __nv_bfloat162* L = (__nv_bfloat162*)lo;
    H[2*i]   = __nv_bfloat162(h0, h1);
    H[2*i+1] = __nv_bfloat162(h2, h3);
    L[2*i]   = __nv_bfloat162(l0, l1);
    L[2*i+1] = __nv_bfloat162(l2, l3);
}

// ---------------------------------------------------------------------------
// Transpose + split: W[K,N] fp32 -> WT_hi[N,K], WT_lo[N,K] bf16
// ---------------------------------------------------------------------------
__global__ __launch_bounds__(256) void transpose_split(
    const float* __restrict__ W, __nv_bfloat16* __restrict__ Thi,
    __nv_bfloat16* __restrict__ Tlo, int K, int N)
{
    __shared__ float t[32][33];
    int tx = threadIdx.x & 31, ty = threadIdx.x >> 5;   // 32x8
    int n0 = blockIdx.x * 32, k0 = blockIdx.y * 32;
    #pragma unroll
    for (int i = 0; i < 32; i += 8)
        t[ty + i][tx] = W[(size_t)(k0 + ty + i) * N + n0 + tx];
    __syncthreads();
    #pragma unroll
    for (int i = 0; i < 32; i += 8) {
        float v = t[tx][ty + i];
        __nv_bfloat16 h = __float2bfloat16(v);
        __nv_bfloat16 l = __float2bfloat16(v - __bfloat162float(h));
        size_t o = (size_t)(n0 + ty + i) * K + k0 + tx;
        Thi[o] = h; Tlo[o] = l;
    }
}

// ---------------------------------------------------------------------------
// HMMA GEMM: C[M,N] = A[M,K] @ B_orig[K,N], B given transposed as Bt[N,K].
// A, Bt in bf16 hi/lo splits; 3 accumulating passes (hi*hi + hi*lo + lo*hi).
// CTA tile 128x128, 8 warps (warp tile 32x64), BK=64, cp.async double buffer.
// SMEM rows padded to 72 bf16 (144B) -> conflict-free ldmatrix.
// Each tile = 128 rows x 8 segs of 16B -> 1024 segs -> 4 per thread. (R6 bug:
// only 2 were loaded, leaving cols 32-63 uninitialized -> NaN.)
// ---------------------------------------------------------------------------
#define BKp 72
#define TILE_B (128 * BKp * 2)            // one bf16 tile, bytes (18432)
#define STAGE_B (4 * TILE_B)              // Ahi,Alo,Bhi,Blo (73728)
#define GEMM_SMEM (2 * STAGE_B)           // 147456 bytes

__global__ __launch_bounds__(256, 1)
void gemm_hmma(const __nv_bfloat16* __restrict__ Ahi,
               const __nv_bfloat16* __restrict__ Alo,
               const __nv_bfloat16* __restrict__ Bhi,
               const __nv_bfloat16* __restrict__ Blo,
               float* __restrict__ C, int M, int N, int K)
{
    extern __shared__ char smem[];
    const uint32_t sb = smem_u32(smem);
    const int tid = threadIdx.x;
    const int m0 = blockIdx.y * 128, n0 = blockIdx.x * 128;
    const int l = tid & 31, w = tid >> 5;
    const int wm = (w & 3) * 32, wn = (w >> 2) * 64;
    const int NCH = K >> 6;

    float acc[2][8][4];
    #pragma unroll
    for (int mt = 0; mt < 2; mt++)
        #pragma unroll
        for (int nt = 0; nt < 8; nt++)
            #pragma unroll
            for (int e = 0; e < 4; e++) acc[mt][nt][e] = 0.0f;

    const __nv_bfloat16* srcs[4] = {Ahi, Alo, Bhi, Blo};

    // ---- prologue: load chunk 0 into stage 0 (full tile coverage)
    #pragma unroll
    for (int a = 0; a < 4; a++) {
        const __nv_bfloat16* src = srcs[a];
        const int rb = (a < 2) ? m0 : n0;
        #pragma unroll
        for (int it = 0; it < 4; it++) {
            int i = tid + it * 256;          // 0..1023
            int r = i >> 3, s = i & 7;       // r: 0..127, s: 0..7
            CP_ASYNC16(sb + a * TILE_B + (r * BKp + s * 8) * 2,
                       src + (size_t)(rb + r) * K + (s << 3));
        }
    }
    CP_COMMIT();

    for (int c = 0; c < NCH; c++) {
        if (c + 1 < NCH) {                    // prefetch next chunk
            const uint32_t st = ((c + 1) & 1) * STAGE_B;
            #pragma unroll
            for (int a = 0; a < 4; a++) {
                const __nv_bfloat16* src = srcs[a];
                const int rb = (a < 2) ? m0 : n0;
                #pragma unroll
                for (int it = 0; it < 4; it++) {
                    int i = tid + it * 256;
                    int r = i >> 3, s = i & 7;
                    CP_ASYNC16(sb + st + a * TILE_B + (r * BKp + s * 8) * 2,
                               src + (size_t)(rb + r) * K + ((c + 1) << 6) + (s << 3));
                }
            }
            CP_COMMIT();
            CP_WAIT1();
        } else {
            CP_WAIT0();
        }
        __syncthreads();

        const uint32_t sbase = sb + (c & 1) * STAGE_B;
        #pragma unroll
        for (int pass = 0; pass < 3; pass++) {
            const uint32_t aoff = sbase + (pass == 2 ? TILE_B : 0);
            const uint32_t boff = sbase + (pass == 1 ? 3 * TILE_B : 2 * TILE_B);
            #pragma unroll
            for (int kb = 0; kb < 64; kb += 16) {
                uint32_t af[2][4], bf[8][2];
                #pragma unroll
                for (int mt = 0; mt < 2; mt++) {
                    int row = wm + mt * 16 + (l & 15);
                    int col = kb + ((l & 16) >> 1);
                    ldsm4(af[mt], aoff + (row * BKp + col) * 2);
                }
                #pragma unroll
                for (int nt2 = 0; nt2 < 4; nt2++) {
                    int row = wn + nt2 * 16 + (l & 7) + ((l & 16) >> 1);
                    int col = kb + (l & 8);
                    uint32_t r4[4];
                    ldsm4(r4, boff + (row * BKp + col) * 2);
                    bf[nt2 * 2][0] = r4[0];  bf[nt2 * 2][1] = r4[1];
                    bf[nt2 * 2 + 1][0] = r4[2];  bf[nt2 * 2 + 1][1] = r4[3];
                }
                #pragma unroll
                for (int mt = 0; mt < 2; mt++)
                    #pragma unroll
                    for (int nt = 0; nt < 8; nt++)
                        mma16816(acc[mt][nt], af[mt], bf[nt]);
            }
        }
        __syncthreads();
    }

    // ---- epilogue: D frag: d0,d1 = (row l>>2, col (l&3)*2 +0/1); d2,d3 = row+8
    #pragma unroll
    for (int mt = 0; mt < 2; mt++) {
        int row = m0 + wm + mt * 16 + (l >> 2);
        #pragma unroll
        for (int nt = 0; nt < 8; nt++) {
            int col = n0 + wn + nt * 8 + (l & 3) * 2;
            *(float2*)&C[(size_t)row * N + col] =
                make_float2(acc[mt][nt][0], acc[mt][nt][1]);
            *(float2*)&C[(size_t)(row + 8) * N + col] =
                make_float2(acc[mt][nt][2], acc[mt][nt][3]);
        }
    }
}

// ---------------------------------------------------------------------------
// Flash attention (fp32, online softmax) — unchanged (verified passing in R2).
// ---------------------------------------------------------------------------
#define BQ 64
#define BKV 64
#define FLASH_SMEM ((128*64 + 128*64 + 64*128 + 64*64) * 4)

__global__ __launch_bounds__(256) void flash_attn(
    const float* __restrict__ Q, const float* __restrict__ Kg,
    const float* __restrict__ Vg, float* __restrict__ Og)
{
    extern __shared__ float sm[];
    float* Qs = sm;
    float* Ks = Qs + 128 * 64;
    float* Vs = Ks + 128 * 64;
    float* Ps = Vs + 64 * 128;

    const int qb = blockIdx.x;
    const int h  = blockIdx.y;
    const int b  = blockIdx.z;
    const int kvh = h >> 2;
    const int tid = threadIdx.x;
    const int rg = tid >> 3;
    const int cg = tid & 7;
    const int r0 = rg * 2;
    const float scale = 0.08838834764831845f;

    for (int i = tid; i < BQ * 32; i += 256) {
        int r  = i >> 5;
        int d4 = (i & 31) << 2;
        int q  = qb * BQ + r;
        float4 v4 = *(const float4*)&Q[(((b * SEQ + q) * HQ + h) << 7) + d4];
        Qs[(d4 + 0) * 64 + r] = v4.x * scale;
        Qs[(d4 + 1) * 64 + r] = v4.y * scale;
        Qs[(d4 + 2) * 64 + r] = v4.z * scale;
        Qs[(d4 + 3) * 64 + r] = v4.w * scale;
    }

    float o[2][16];
    #pragma unroll
    for (int i = 0; i < 2; i++)
        #pragma unroll
        for (int t = 0; t < 16; t++) o[i][t] = 0.0f;
    float mr[2] = {-1e30f, -1e30f};
    float lr[2] = {0.0f, 0.0f};

    const int qg0 = qb * BQ + r0;
    const int kc0 = cg * 8;

    const int nkb = qb + 1;
    for (int kb = 0; kb < nkb; kb++) {
        __syncthreads();
        for (int i = tid; i < BKV * 32; i += 256) {
            int r  = i >> 5;
            int d4 = (i & 31) << 2;
            int kk = kb * BKV + r;
            int base = ((b * SEQ + kk) * HKV + kvh) * HD + d4;
            float4 k4 = *(const float4*)&Kg[base];
            Ks[(d4 + 0) * 64 + r] = k4.x;
            Ks[(d4 + 1) * 64 + r] = k4.y;
            Ks[(d4 + 2) * 64 + r] = k4.z;
            Ks[(d4 + 3) * 64 + r] = k4.w;
            float4 vv = *(const float4*)&Vg[base];
            *(float4*)&Vs[r * 128 + d4] = vv;
        }
        __syncthreads();

        float s[2][8];
        #pragma unroll
        for (int i = 0; i < 2; i++)
            #pragma unroll
            for (int j = 0; j < 8; j++) s[i][j] = 0.0f;

        #pragma unroll 4
        for (int d = 0; d < 128; d++) {
            float2 q2 = *(const float2*)&Qs[d * 64 + r0];
            float4 ka = *(const float4*)&Ks[d * 64 + kc0];
            float4 kb4 = *(const float4*)&Ks[d * 64 + kc0 + 4];
            float kf[8] = {ka.x, ka.y, ka.z, ka.w, kb4.x, kb4.y, kb4.z, kb4.w};
            #pragma unroll
            for (int j = 0; j < 8; j++) {
                s[0][j] += q2.x * kf[j];
                s[1][j] += q2.y * kf[j];
            }
        }

        if (kb == qb) {
            int kg0 = kb * BKV + kc0;
            #pragma unroll
            for (int i = 0; i < 2; i++)
                #pragma unroll
                for (int j = 0; j < 8; j++)
                    if (kg0 + j > qg0 + i) s[i][j] = -1e30f;
        }

        #pragma unroll
        for (int i = 0; i < 2; i++) {
            float mx = s[i][0];
            #pragma unroll
            for (int j = 1; j < 8; j++) mx = fmaxf(mx, s[i][j]);
            #pragma unroll
            for (int off = 1; off < 8; off <<= 1)
                mx = fmaxf(mx, __shfl_xor_sync(0xffffffffu, mx, off));
            float mnew = fmaxf(mr[i], mx);
            float corr = __expf(mr[i] - mnew);
            mr[i] = mnew;
            float ps = 0.0f;
            #pragma unroll
            for (int j = 0; j < 8; j++) {
                float p = __expf(s[i][j] - mnew);
                ps += p;
                Ps[(kc0 + j) * 64 + r0 + i] = p;
            }
            #pragma unroll
            for (int off = 1; off < 8; off <<= 1)
                ps += __shfl_xor_sync(0xffffffffu, ps, off);
            lr[i] = lr[i] * corr + ps;
            #pragma unroll
            for (int t = 0; t < 16; t++) o[i][t] *= corr;
        }
        __syncwarp();

        #pragma unroll 2
        for (int kk = 0; kk < BKV; kk++) {
            float2 p2 = *(const float2*)&Ps[kk * 64 + r0];
            const float* vrow = &Vs[kk * 128 + cg * 16];
            float4 v0 = *(const float4*)&vrow[0];
            float4 v1 = *(const float4*)&vrow[4];
            float4 v2 = *(const float4*)&vrow[8];
            float4 v3 = *(const float4*)&vrow[12];
            float vf[16] = {v0.x, v0.y, v0.z, v0.w, v1.x, v1.y, v1.z, v1.w,
                            v2.x, v2.y, v2.z, v2.w, v3.x, v3.y, v3.z, v3.w};
            #pragma unroll
            for (int t = 0; t < 16; t++) {
                o[0][t] += p2.x * vf[t];
                o[1][t] += p2.y * vf[t];
            }
        }
    }

    #pragma unroll
    for (int i = 0; i < 2; i++) {
        float inv = 1.0f / lr[i];
        int q = qb * BQ + r0 + i;
        float* outp = &Og[(((b * SEQ + q) * HQ + h) << 7) + cg * 16];
        #pragma unroll
        for (int t4 = 0; t4 < 4; t4++) {
            float4 wv = make_float4(o[i][4*t4+0] * inv, o[i][4*t4+1] * inv,
                                    o[i][4*t4+2] * inv, o[i][4*t4+3] * inv);
            *(float4*)&outp[4 * t4] = wv;
        }
    }
}

// ---------------------------------------------------------------------------
extern "C" void kernel_launch(void* const* d_in, const int* in_sizes, int n_in,
                              void* d_out, int out_size)
{
    const float* x  = (const float*)d_in[0];
    const float* wq = (const float*)d_in[1];
    const float* wk = (const float*)d_in[2];
    const float* wv = (const float*)d_in[3];
    const float* wo = (const float*)d_in[4];
    float* out = (float*)d_out;

    float *q, *k, *v, *att;
    __nv_bfloat16 *xhi, *xlo, *ahi, *alo;
    __nv_bfloat16 *wqThi, *wqTlo, *wkThi, *wkTlo, *wvThi, *wvTlo, *woThi, *woTlo;
    cudaGetSymbolAddress((void**)&q, g_q);
    cudaGetSymbolAddress((void**)&k, g_k);
    cudaGetSymbolAddress((void**)&v, g_v);
    cudaGetSymbolAddress((void**)&att, g_att);
    cudaGetSymbolAddress((void**)&xhi, g_xhi);
    cudaGetSymbolAddress((void**)&xlo, g_xlo);
    cudaGetSymbolAddress((void**)&ahi, g_ahi);
    cudaGetSymbolAddress((void**)&alo, g_alo);
    cudaGetSymbolAddress((void**)&wqThi, g_wqThi);
    cudaGetSymbolAddress((void**)&wqTlo, g_wqTlo);
    cudaGetSymbolAddress((void**)&wkThi, g_wkThi);
    cudaGetSymbolAddress((void**)&wkTlo, g_wkTlo);
    cudaGetSymbolAddress((void**)&wvThi, g_wvThi);
    cudaGetSymbolAddress((void**)&wvTlo, g_wvTlo);
    cudaGetSymbolAddress((void**)&woThi, g_woThi);
    cudaGetSymbolAddress((void**)&woTlo, g_woTlo);

    cudaFuncSetAttribute(flash_attn, cudaFuncAttributeMaxDynamicSharedMemorySize,
                         FLASH_SMEM);
    cudaFuncSetAttribute(gemm_hmma, cudaFuncAttributeMaxDynamicSharedMemorySize,
                         GEMM_SMEM);

    const int n4 = ROWS * DIMV / 4;

    // Preprocess: split activations, transpose+split weights
    split_rm<<<n4 / 256, 256>>>((const float4*)x, xhi, xlo, n4);
    transpose_split<<<dim3(DIMV / 32,  DIMV / 32), 256>>>(wq, wqThi, wqTlo, DIMV, DIMV);
    transpose_split<<<dim3(KVDIM / 32, DIMV / 32), 256>>>(wk, wkThi, wkTlo, DIMV, KVDIM);
    transpose_split<<<dim3(KVDIM / 32, DIMV / 32), 256>>>(wv, wvThi, wvTlo, DIMV, KVDIM);
    transpose_split<<<dim3(DIMV / 32,  DIMV / 32), 256>>>(wo, woThi, woTlo, DIMV, DIMV);

    // Projections on HMMA tensor cores
    gemm_hmma<<<dim3(DIMV / 128,  ROWS / 128), 256, GEMM_SMEM>>>(
        xhi, xlo, wqThi, wqTlo, q, ROWS, DIMV, DIMV);
    gemm_hmma<<<dim3(KVDIM / 128, ROWS / 128), 256, GEMM_SMEM>>>(
        xhi, xlo, wkThi, wkTlo, k, ROWS, KVDIM, DIMV);
    gemm_hmma<<<dim3(KVDIM / 128, ROWS / 128), 256, GEMM_SMEM>>>(
        xhi, xlo, wvThi, wvTlo, v, ROWS, KVDIM, DIMV);

    flash_attn<<<dim3(SEQ / BQ, HQ, BATCH), 256, FLASH_SMEM>>>(q, k, v, att);

    // Output projection
    split_rm<<<n4 / 256, 256>>>((const float4*)att, ahi, alo, n4);
    gemm_hmma<<<dim3(DIMV / 128, ROWS / 128), 256, GEMM_SMEM>>>(
        ahi, alo, woThi, woTlo, out, ROWS, DIMV, DIMV);
}

// round 8
// speedup vs baseline: 4.3994x; 2.8417x over previous
#include <cuda_runtime.h>
#include <cuda_bf16.h>
#include <cstdint>

// Problem constants
#define BATCH   2
#define SEQ     2048
#define DIMV    4096
#define HQ      32
#define HKV     8
#define HD      128
#define ROWS    (BATCH * SEQ)      // 4096
#define KVDIM   (HKV * HD)         // 1024

// ---------------------------------------------------------------------------
// Device scratch (allocation-free rule)
// ---------------------------------------------------------------------------
__device__ __nv_bfloat16 g_xhi[ROWS * DIMV],  g_xlo[ROWS * DIMV];
__device__ __nv_bfloat16 g_qhi[ROWS * DIMV],  g_qlo[ROWS * DIMV];
__device__ __nv_bfloat16 g_khi[ROWS * KVDIM], g_klo[ROWS * KVDIM];
__device__ __nv_bfloat16 g_vhi[ROWS * KVDIM], g_vlo[ROWS * KVDIM];
__device__ __nv_bfloat16 g_ahi[ROWS * DIMV],  g_alo[ROWS * DIMV];
__device__ __nv_bfloat16 g_wqThi[DIMV * DIMV],  g_wqTlo[DIMV * DIMV];
__device__ __nv_bfloat16 g_wkThi[KVDIM * DIMV], g_wkTlo[KVDIM * DIMV];
__device__ __nv_bfloat16 g_wvThi[KVDIM * DIMV], g_wvTlo[KVDIM * DIMV];
__device__ __nv_bfloat16 g_woThi[DIMV * DIMV],  g_woTlo[DIMV * DIMV];

// ---------------------------------------------------------------------------
// Arch-generic PTX helpers (NO 'a'-gated instructions: sm_103 virtual target)
// ---------------------------------------------------------------------------
__device__ __forceinline__ uint32_t smem_u32(const void* p) {
    uint32_t a;
    asm("{ .reg .u64 t; cvta.to.shared.u64 t, %1; cvt.u32.u64 %0, t; }"
        : "=r"(a) : "l"(p));
    return a;
}

#define CP_ASYNC16(saddr, gptr) \
    asm volatile("cp.async.cg.shared.global [%0], [%1], 16;" \
        :: "r"(saddr), "l"(gptr) : "memory")
#define CP_COMMIT()  asm volatile("cp.async.commit_group;" ::: "memory")
#define CP_WAIT1()   asm volatile("cp.async.wait_group 1;" ::: "memory")
#define CP_WAIT0()   asm volatile("cp.async.wait_group 0;" ::: "memory")

__device__ __forceinline__ void ldsm4(uint32_t* r, uint32_t addr) {
    asm volatile("ldmatrix.sync.aligned.m8n8.x4.shared.b16 {%0,%1,%2,%3}, [%4];"
        : "=r"(r[0]), "=r"(r[1]), "=r"(r[2]), "=r"(r[3]) : "r"(addr));
}
__device__ __forceinline__ void ldsm4t(uint32_t* r, uint32_t addr) {
    asm volatile("ldmatrix.sync.aligned.m8n8.x4.trans.shared.b16 {%0,%1,%2,%3}, [%4];"
        : "=r"(r[0]), "=r"(r[1]), "=r"(r[2]), "=r"(r[3]) : "r"(addr));
}

__device__ __forceinline__ void mma16816(float* d, const uint32_t* a, const uint32_t* b) {
    asm volatile("mma.sync.aligned.m16n8k16.row.col.f32.bf16.bf16.f32 "
        "{%0,%1,%2,%3}, {%4,%5,%6,%7}, {%8,%9}, {%0,%1,%2,%3};"
        : "+f"(d[0]), "+f"(d[1]), "+f"(d[2]), "+f"(d[3])
        : "r"(a[0]), "r"(a[1]), "r"(a[2]), "r"(a[3]), "r"(b[0]), "r"(b[1]));
}
__device__ __forceinline__ void mma2(float* d, const uint32_t* a, uint32_t b0, uint32_t b1) {
    asm volatile("mma.sync.aligned.m16n8k16.row.col.f32.bf16.bf16.f32 "
        "{%0,%1,%2,%3}, {%4,%5,%6,%7}, {%8,%9}, {%0,%1,%2,%3};"
        : "+f"(d[0]), "+f"(d[1]), "+f"(d[2]), "+f"(d[3])
        : "r"(a[0]), "r"(a[1]), "r"(a[2]), "r"(a[3]), "r"(b0), "r"(b1));
}

__device__ __forceinline__ uint32_t pack_split2(float a, float b, uint32_t& lo_out) {
    __nv_bfloat16 ha = __float2bfloat16(a), hb = __float2bfloat16(b);
    __nv_bfloat16 la = __float2bfloat16(a - __bfloat162float(ha));
    __nv_bfloat16 lb = __float2bfloat16(b - __bfloat162float(hb));
    __nv_bfloat162 H(ha, hb), L(la, lb);
    lo_out = *(uint32_t*)&L;
    return *(uint32_t*)&H;
}

// ---------------------------------------------------------------------------
// Split fp32 -> bf16 hi/lo (row-major, elementwise)
// ---------------------------------------------------------------------------
__global__ __launch_bounds__(256) void split_rm(
    const float4* __restrict__ in, __nv_bfloat16* __restrict__ hi,
    __nv_bfloat16* __restrict__ lo, int n4)
{
    int i = blockIdx.x * 256 + threadIdx.x;
    if (i >= n4) return;
    float4 v = in[i];
    uint32_t l0, l1;
    uint32_t h0 = pack_split2(v.x, v.y, l0);
    uint32_t h1 = pack_split2(v.z, v.w, l1);
    uint32_t* H = (uint32_t*)hi;
    uint32_t* L = (uint32_t*)lo;
    H[2*i] = h0; H[2*i+1] = h1;
    L[2*i] = l0; L[2*i+1] = l1;
}

// ---------------------------------------------------------------------------
// Transpose + split: W[K,N] fp32 -> WT_hi[N,K], WT_lo[N,K] bf16
// ---------------------------------------------------------------------------
__global__ __launch_bounds__(256) void transpose_split(
    const float* __restrict__ W, __nv_bfloat16* __restrict__ Thi,
    __nv_bfloat16* __restrict__ Tlo, int K, int N)
{
    __shared__ float t[32][33];
    int tx = threadIdx.x & 31, ty = threadIdx.x >> 5;   // 32x8
    int n0 = blockIdx.x * 32, k0 = blockIdx.y * 32;
    #pragma unroll
    for (int i = 0; i < 32; i += 8)
        t[ty + i][tx] = W[(size_t)(k0 + ty + i) * N + n0 + tx];
    __syncthreads();
    #pragma unroll
    for (int i = 0; i < 32; i += 8) {
        float v = t[tx][ty + i];
        __nv_bfloat16 h = __float2bfloat16(v);
        __nv_bfloat16 l = __float2bfloat16(v - __bfloat162float(h));
        size_t o = (size_t)(n0 + ty + i) * K + k0 + tx;
        Thi[o] = h; Tlo[o] = l;
    }
}

// ---------------------------------------------------------------------------
// HMMA GEMM: C = A @ Bt^T, A/Bt bf16 hi/lo; 3 passes. Output either fp32 (Cf)
// or fused-split bf16 hi/lo (Chi/Clo) when Cf == nullptr.
// CTA 128x128, 8 warps (32x64), BK=64, cp.async double buffer, rows padded 72.
// ---------------------------------------------------------------------------
#define BKp 72
#define TILE_B (128 * BKp * 2)
#define STAGE_B (4 * TILE_B)
#define GEMM_SMEM (2 * STAGE_B)

__global__ __launch_bounds__(256, 1)
void gemm_hmma(const __nv_bfloat16* __restrict__ Ahi,
               const __nv_bfloat16* __restrict__ Alo,
               const __nv_bfloat16* __restrict__ Bhi,
               const __nv_bfloat16* __restrict__ Blo,
               float* __restrict__ Cf,
               __nv_bfloat16* __restrict__ Chi, __nv_bfloat16* __restrict__ Clo,
               int M, int N, int K)
{
    extern __shared__ char smem[];
    const uint32_t sb = smem_u32(smem);
    const int tid = threadIdx.x;
    const int m0 = blockIdx.y * 128, n0 = blockIdx.x * 128;
    const int l = tid & 31, w = tid >> 5;
    const int wm = (w & 3) * 32, wn = (w >> 2) * 64;
    const int NCH = K >> 6;

    float acc[2][8][4];
    #pragma unroll
    for (int mt = 0; mt < 2; mt++)
        #pragma unroll
        for (int nt = 0; nt < 8; nt++)
            #pragma unroll
            for (int e = 0; e < 4; e++) acc[mt][nt][e] = 0.0f;

    const __nv_bfloat16* srcs[4] = {Ahi, Alo, Bhi, Blo};

    #pragma unroll
    for (int a = 0; a < 4; a++) {
        const __nv_bfloat16* src = srcs[a];
        const int rb = (a < 2) ? m0 : n0;
        #pragma unroll
        for (int it = 0; it < 4; it++) {
            int i = tid + it * 256;
            int r = i >> 3, s = i & 7;
            CP_ASYNC16(sb + a * TILE_B + (r * BKp + s * 8) * 2,
                       src + (size_t)(rb + r) * K + (s << 3));
        }
    }
    CP_COMMIT();

    for (int c = 0; c < NCH; c++) {
        if (c + 1 < NCH) {
            const uint32_t st = ((c + 1) & 1) * STAGE_B;
            #pragma unroll
            for (int a = 0; a < 4; a++) {
                const __nv_bfloat16* src = srcs[a];
                const int rb = (a < 2) ? m0 : n0;
                #pragma unroll
                for (int it = 0; it < 4; it++) {
                    int i = tid + it * 256;
                    int r = i >> 3, s = i & 7;
                    CP_ASYNC16(sb + st + a * TILE_B + (r * BKp + s * 8) * 2,
                               src + (size_t)(rb + r) * K + ((c + 1) << 6) + (s << 3));
                }
            }
            CP_COMMIT();
            CP_WAIT1();
        } else {
            CP_WAIT0();
        }
        __syncthreads();

        const uint32_t sbase = sb + (c & 1) * STAGE_B;
        #pragma unroll
        for (int pass = 0; pass < 3; pass++) {
            const uint32_t aoff = sbase + (pass == 2 ? TILE_B : 0);
            const uint32_t boff = sbase + (pass == 1 ? 3 * TILE_B : 2 * TILE_B);
            #pragma unroll
            for (int kb = 0; kb < 64; kb += 16) {
                uint32_t af[2][4], bf[8][2];
                #pragma unroll
                for (int mt = 0; mt < 2; mt++) {
                    int row = wm + mt * 16 + (l & 15);
                    int col = kb + ((l & 16) >> 1);
                    ldsm4(af[mt], aoff + (row * BKp + col) * 2);
                }
                #pragma unroll
                for (int nt2 = 0; nt2 < 4; nt2++) {
                    int row = wn + nt2 * 16 + (l & 7) + ((l & 16) >> 1);
                    int col = kb + (l & 8);
                    uint32_t r4[4];
                    ldsm4(r4, boff + (row * BKp + col) * 2);
                    bf[nt2 * 2][0] = r4[0];  bf[nt2 * 2][1] = r4[1];
                    bf[nt2 * 2 + 1][0] = r4[2];  bf[nt2 * 2 + 1][1] = r4[3];
                }
                #pragma unroll
                for (int mt = 0; mt < 2; mt++)
                    #pragma unroll
                    for (int nt = 0; nt < 8; nt++)
                        mma16816(acc[mt][nt], af[mt], bf[nt]);
            }
        }
        __syncthreads();
    }

    #pragma unroll
    for (int mt = 0; mt < 2; mt++) {
        int row = m0 + wm + mt * 16 + (l >> 2);
        #pragma unroll
        for (int nt = 0; nt < 8; nt++) {
            int col = n0 + wn + nt * 8 + (l & 3) * 2;
            if (Cf) {
                *(float2*)&Cf[(size_t)row * N + col] =
                    make_float2(acc[mt][nt][0], acc[mt][nt][1]);
                *(float2*)&Cf[(size_t)(row + 8) * N + col] =
                    make_float2(acc[mt][nt][2], acc[mt][nt][3]);
            } else {
                uint32_t lo;
                uint32_t hi = pack_split2(acc[mt][nt][0], acc[mt][nt][1], lo);
                *(uint32_t*)&Chi[(size_t)row * N + col] = hi;
                *(uint32_t*)&Clo[(size_t)row * N + col] = lo;
                hi = pack_split2(acc[mt][nt][2], acc[mt][nt][3], lo);
                *(uint32_t*)&Chi[(size_t)(row + 8) * N + col] = hi;
                *(uint32_t*)&Clo[(size_t)(row + 8) * N + col] = lo;
            }
        }
    }
}

// ---------------------------------------------------------------------------
// HMMA flash attention: BQ=128 q/CTA (8 warps x 16), BKV=64, d=128 resident.
// Q in SMEM (hi/lo), K/V double-buffered. S via 3-pass m16n8k16; softmax fp32
// on fragments; P split hi/lo in regs (FA2 S->A frag trick); V via ldsm.trans.
// Writes attention output directly as bf16 hi/lo splits.
// ---------------------------------------------------------------------------
#define BQ2 128
#define BKV2 64
#define SQel 136                 // padded row stride (bf16 elements), 272 B
#define F_QHI 0
#define F_QLO 34816
#define F_STAGE0 69632
#define F_STAGE_SZ 69632         // khi,klo,vhi,vlo each 64*136*2 = 17408 B
#define FLASH2_SMEM (F_STAGE0 + 2 * F_STAGE_SZ)   // 208896 B

__global__ __launch_bounds__(256, 1)
void flash_hmma(const __nv_bfloat16* __restrict__ Qhi, const __nv_bfloat16* __restrict__ Qlo,
                const __nv_bfloat16* __restrict__ Khi, const __nv_bfloat16* __restrict__ Klo,
                const __nv_bfloat16* __restrict__ Vhi, const __nv_bfloat16* __restrict__ Vlo,
                __nv_bfloat16* __restrict__ Ahi, __nv_bfloat16* __restrict__ Alo)
{
    extern __shared__ char smem[];
    const uint32_t sb = smem_u32(smem);
    const int qb = blockIdx.x, h = blockIdx.y, b = blockIdx.z;
    const int kvh = h >> 2;
    const int tid = threadIdx.x;
    const int l = tid & 31, w = tid >> 5;
    const int wq = w * 16;
    const float scale = 0.08838834764831845f;   // 1/sqrt(128)

    // Q load (once): 2 tiles x 128 rows x 16 segs of 16B
    #pragma unroll
    for (int it = 0; it < 16; it++) {
        int idx = tid + it * 256;
        int t = idx >> 11, r = (idx >> 4) & 127, s = idx & 15;
        const __nv_bfloat16* src = t ? Qlo : Qhi;
        size_t grow = ((size_t)(b * SEQ + qb * BQ2 + r) * HQ + h) * HD;
        CP_ASYNC16(sb + (t ? F_QLO : F_QHI) + (r * SQel + s * 8) * 2, src + grow + s * 8);
    }
    // K/V stage 0
    const __nv_bfloat16* kvsrc[4] = {Khi, Klo, Vhi, Vlo};
    #pragma unroll
    for (int it = 0; it < 16; it++) {
        int idx = tid + it * 256;
        int t = idx >> 10, r = (idx >> 4) & 63, s = idx & 15;
        size_t grow = ((size_t)(b * SEQ + r) * HKV + kvh) * HD;
        CP_ASYNC16(sb + F_STAGE0 + t * 17408 + (r * SQel + s * 8) * 2, kvsrc[t] + grow + s * 8);
    }
    CP_COMMIT();

    float oacc[16][4];
    #pragma unroll
    for (int nt = 0; nt < 16; nt++)
        #pragma unroll
        for (int e = 0; e < 4; e++) oacc[nt][e] = 0.0f;
    float m0 = -1e30f, m1 = -1e30f, lsum0 = 0.0f, lsum1 = 0.0f;
    const int qg0 = qb * BQ2 + wq + (l >> 2);

    const int niter = 2 * (qb + 1);
    for (int kt = 0; kt < niter; kt++) {
        if (kt + 1 < niter) {
            uint32_t st = sb + F_STAGE0 + ((kt + 1) & 1) * F_STAGE_SZ;
            #pragma unroll
            for (int it = 0; it < 16; it++) {
                int idx = tid + it * 256;
                int t = idx >> 10, r = (idx >> 4) & 63, s = idx & 15;
                size_t grow = ((size_t)(b * SEQ + (kt + 1) * BKV2 + r) * HKV + kvh) * HD;
                CP_ASYNC16(st + t * 17408 + (r * SQel + s * 8) * 2, kvsrc[t] + grow + s * 8);
            }
            CP_COMMIT();
            CP_WAIT1();
        } else {
            CP_WAIT0();
        }
        __syncthreads();
        const uint32_t kb = sb + F_STAGE0 + (kt & 1) * F_STAGE_SZ;

        // ---- S = Q.K^T (16x64 per warp), 3 passes
        float sacc[8][4];
        #pragma unroll
        for (int nt = 0; nt < 8; nt++)
            #pragma unroll
            for (int e = 0; e < 4; e++) sacc[nt][e] = 0.0f;

        #pragma unroll
        for (int ks = 0; ks < 8; ks++) {
            uint32_t ahi[4], alo[4];
            uint32_t aaddr = ((wq + (l & 15)) * SQel + ks * 16 + ((l & 16) >> 1)) * 2;
            ldsm4(ahi, sb + F_QHI + aaddr);
            ldsm4(alo, sb + F_QLO + aaddr);
            uint32_t bhi[8][2], blo[8][2];
            #pragma unroll
            for (int nt2 = 0; nt2 < 4; nt2++) {
                int row = nt2 * 16 + (l & 7) + ((l & 16) >> 1);
                int col = ks * 16 + (l & 8);
                uint32_t r4[4];
                ldsm4(r4, kb + (row * SQel + col) * 2);
                bhi[nt2*2][0] = r4[0]; bhi[nt2*2][1] = r4[1];
                bhi[nt2*2+1][0] = r4[2]; bhi[nt2*2+1][1] = r4[3];
                ldsm4(r4, kb + 17408 + (row * SQel + col) * 2);
                blo[nt2*2][0] = r4[0]; blo[nt2*2][1] = r4[1];
                blo[nt2*2+1][0] = r4[2]; blo[nt2*2+1][1] = r4[3];
            }
            #pragma unroll
            for (int nt = 0; nt < 8; nt++) {
                mma16816(sacc[nt], ahi, bhi[nt]);
                mma16816(sacc[nt], ahi, blo[nt]);
                mma16816(sacc[nt], alo, bhi[nt]);
            }
        }

        // ---- softmax (fp32, fragment-level)
        const bool domask = (kt >= 2 * qb);
        #pragma unroll
        for (int nt = 0; nt < 8; nt++)
            #pragma unroll
            for (int e = 0; e < 4; e++) {
                float s = sacc[nt][e] * scale;
                if (domask) {
                    int kg = kt * BKV2 + nt * 8 + (l & 3) * 2 + (e & 1);
                    int qg = qg0 + ((e >= 2) ? 8 : 0);
                    if (kg > qg) s = -1e30f;
                }
                sacc[nt][e] = s;
            }
        float mx0 = -1e30f, mx1 = -1e30f;
        #pragma unroll
        for (int nt = 0; nt < 8; nt++) {
            mx0 = fmaxf(mx0, fmaxf(sacc[nt][0], sacc[nt][1]));
            mx1 = fmaxf(mx1, fmaxf(sacc[nt][2], sacc[nt][3]));
        }
        mx0 = fmaxf(mx0, __shfl_xor_sync(0xffffffffu, mx0, 1));
        mx0 = fmaxf(mx0, __shfl_xor_sync(0xffffffffu, mx0, 2));
        mx1 = fmaxf(mx1, __shfl_xor_sync(0xffffffffu, mx1, 1));
        mx1 = fmaxf(mx1, __shfl_xor_sync(0xffffffffu, mx1, 2));
        float mn0 = fmaxf(m0, mx0), mn1 = fmaxf(m1, mx1);
        float c0 = __expf(m0 - mn0), c1 = __expf(m1 - mn1);
        m0 = mn0; m1 = mn1;
        float ps0 = 0.0f, ps1 = 0.0f;
        #pragma unroll
        for (int nt = 0; nt < 8; nt++) {
            float p0 = __expf(sacc[nt][0] - mn0), p1 = __expf(sacc[nt][1] - mn0);
            float p2 = __expf(sacc[nt][2] - mn1), p3 = __expf(sacc[nt][3] - mn1);
            ps0 += p0 + p1; ps1 += p2 + p3;
            sacc[nt][0] = p0; sacc[nt][1] = p1; sacc[nt][2] = p2; sacc[nt][3] = p3;
        }
        ps0 += __shfl_xor_sync(0xffffffffu, ps0, 1);
        ps0 += __shfl_xor_sync(0xffffffffu, ps0, 2);
        ps1 += __shfl_xor_sync(0xffffffffu, ps1, 1);
        ps1 += __shfl_xor_sync(0xffffffffu, ps1, 2);
        lsum0 = lsum0 * c0 + ps0;
        lsum1 = lsum1 * c1 + ps1;
        #pragma unroll
        for (int nt = 0; nt < 16; nt++) {
            oacc[nt][0] *= c0; oacc[nt][1] *= c0;
            oacc[nt][2] *= c1; oacc[nt][3] *= c1;
        }

        // ---- O += P.V (P from S-frags reinterpreted as A-frags, split hi/lo)
        #pragma unroll
        for (int j = 0; j < 4; j++) {
            uint32_t phi[4], plo[4];
            phi[0] = pack_split2(sacc[2*j][0],   sacc[2*j][1],   plo[0]);
            phi[1] = pack_split2(sacc[2*j][2],   sacc[2*j][3],   plo[1]);
            phi[2] = pack_split2(sacc[2*j+1][0], sacc[2*j+1][1], plo[2]);
            phi[3] = pack_split2(sacc[2*j+1][2], sacc[2*j+1][3], plo[3]);
            #pragma unroll
            for (int np = 0; np < 8; np++) {
                uint32_t vaddr = ((j * 16 + (l & 15)) * SQel + np * 16 + ((l & 16) >> 1)) * 2;
                uint32_t vh[4], vl[4];
                ldsm4t(vh, kb + 34816 + vaddr);
                ldsm4t(vl, kb + 52224 + vaddr);
                mma2(oacc[2*np],   phi, vh[0], vh[1]);
                mma2(oacc[2*np],   phi, vl[0], vl[1]);
                mma2(oacc[2*np],   plo, vh[0], vh[1]);
                mma2(oacc[2*np+1], phi, vh[2], vh[3]);
                mma2(oacc[2*np+1], phi, vl[2], vl[3]);
                mma2(oacc[2*np+1], plo, vh[2], vh[3]);
            }
        }
        __syncthreads();
    }

    // ---- epilogue: normalize, split to bf16 hi/lo, write [B,S,HQ,HD]
    float inv0 = 1.0f / lsum0, inv1 = 1.0f / lsum1;
    size_t base0 = ((size_t)(b * SEQ + qg0) * HQ + h) * HD;
    size_t base1 = base0 + (size_t)8 * HQ * HD;
    #pragma unroll
    for (int nt = 0; nt < 16; nt++) {
        int col = nt * 8 + (l & 3) * 2;
        uint32_t lo;
        uint32_t hi = pack_split2(oacc[nt][0] * inv0, oacc[nt][1] * inv0, lo);
        *(uint32_t*)&Ahi[base0 + col] = hi;
        *(uint32_t*)&Alo[base0 + col] = lo;
        hi = pack_split2(oacc[nt][2] * inv1, oacc[nt][3] * inv1, lo);
        *(uint32_t*)&Ahi[base1 + col] = hi;
        *(uint32_t*)&Alo[base1 + col] = lo;
    }
}

// ---------------------------------------------------------------------------
extern "C" void kernel_launch(void* const* d_in, const int* in_sizes, int n_in,
                              void* d_out, int out_size)
{
    const float* x  = (const float*)d_in[0];
    const float* wq = (const float*)d_in[1];
    const float* wk = (const float*)d_in[2];
    const float* wv = (const float*)d_in[3];
    const float* wo = (const float*)d_in[4];
    float* out = (float*)d_out;

    __nv_bfloat16 *xhi, *xlo, *qhi, *qlo, *khi, *klo, *vhi, *vlo, *ahi, *alo;
    __nv_bfloat16 *wqThi, *wqTlo, *wkThi, *wkTlo, *wvThi, *wvTlo, *woThi, *woTlo;
    cudaGetSymbolAddress((void**)&xhi, g_xhi);
    cudaGetSymbolAddress((void**)&xlo, g_xlo);
    cudaGetSymbolAddress((void**)&qhi, g_qhi);
    cudaGetSymbolAddress((void**)&qlo, g_qlo);
    cudaGetSymbolAddress((void**)&khi, g_khi);
    cudaGetSymbolAddress((void**)&klo, g_klo);
    cudaGetSymbolAddress((void**)&vhi, g_vhi);
    cudaGetSymbolAddress((void**)&vlo, g_vlo);
    cudaGetSymbolAddress((void**)&ahi, g_ahi);
    cudaGetSymbolAddress((void**)&alo, g_alo);
    cudaGetSymbolAddress((void**)&wqThi, g_wqThi);
    cudaGetSymbolAddress((void**)&wqTlo, g_wqTlo);
    cudaGetSymbolAddress((void**)&wkThi, g_wkThi);
    cudaGetSymbolAddress((void**)&wkTlo, g_wkTlo);
    cudaGetSymbolAddress((void**)&wvThi, g_wvThi);
    cudaGetSymbolAddress((void**)&wvTlo, g_wvTlo);
    cudaGetSymbolAddress((void**)&woThi, g_woThi);
    cudaGetSymbolAddress((void**)&woTlo, g_woTlo);

    cudaFuncSetAttribute(gemm_hmma, cudaFuncAttributeMaxDynamicSharedMemorySize,
                         GEMM_SMEM);
    cudaFuncSetAttribute(flash_hmma, cudaFuncAttributeMaxDynamicSharedMemorySize,
                         FLASH2_SMEM);

    const int n4 = ROWS * DIMV / 4;

    split_rm<<<n4 / 256, 256>>>((const float4*)x, xhi, xlo, n4);
    transpose_split<<<dim3(DIMV / 32,  DIMV / 32), 256>>>(wq, wqThi, wqTlo, DIMV, DIMV);
    transpose_split<<<dim3(KVDIM / 32, DIMV / 32), 256>>>(wk, wkThi, wkTlo, DIMV, KVDIM);
    transpose_split<<<dim3(KVDIM / 32, DIMV / 32), 256>>>(wv, wvThi, wvTlo, DIMV, KVDIM);
    transpose_split<<<dim3(DIMV / 32,  DIMV / 32), 256>>>(wo, woThi, woTlo, DIMV, DIMV);

    // Projections: fused split-output epilogues
    gemm_hmma<<<dim3(DIMV / 128,  ROWS / 128), 256, GEMM_SMEM>>>(
        xhi, xlo, wqThi, wqTlo, nullptr, qhi, qlo, ROWS, DIMV, DIMV);
    gemm_hmma<<<dim3(KVDIM / 128, ROWS / 128), 256, GEMM_SMEM>>>(
        xhi, xlo, wkThi, wkTlo, nullptr, khi, klo, ROWS, KVDIM, DIMV);
    gemm_hmma<<<dim3(KVDIM / 128, ROWS / 128), 256, GEMM_SMEM>>>(
        xhi, xlo, wvThi, wvTlo, nullptr, vhi, vlo, ROWS, KVDIM, DIMV);

    flash_hmma<<<dim3(SEQ / BQ2, HQ, BATCH), 256, FLASH2_SMEM>>>(
        qhi, qlo, khi, klo, vhi, vlo, ahi, alo);

    gemm_hmma<<<dim3(DIMV / 128, ROWS / 128), 256, GEMM_SMEM>>>(
        ahi, alo, woThi, woTlo, out, nullptr, nullptr, ROWS, DIMV, DIMV);
}